// round 8
// baseline (speedup 1.0000x reference)
#include <cuda_runtime.h>
#include <cuda_bf16.h>
#include <math.h>

// Problem constants
#define Bn   16
#define Cc   256
#define HWn  4096
#define NHh  4
#define HDd  64
#define CHW  1048576L   // C*HW
#define NSPL 8          // n-split slabs for attention scores

// ---------------- scratch (static __device__ — no allocation allowed) ----------------
__device__ float g_q[16777216];      // (B,256,HW)
__device__ float g_kv[67108864];     // (2B,512,HW)
__device__ float g_attn[16777216];   // (B,256,HW)
__device__ float g_x[16777216];      // residual mid
__device__ float g_y1[16777216];
__device__ float g_y2[16777216];
__device__ float g_S[NSPL*64*64*128];   // score partials [slab][bh][c][dd]
__device__ float g_qn2[NSPL*64*64];
__device__ float g_kn2[NSPL*64*128];
__device__ float g_P[64*64*128];        // gated softmax probs [bh][c][dd]
__device__ float g_muq[65536],  g_rsq[65536];
__device__ float g_mukv[131072],g_rskv[131072];
__device__ float g_mux[65536],  g_rsx[65536];
__device__ float g_Wq[65536],  g_Sq[256],  g_Bq[256];
__device__ float g_Wkv[131072],g_Skv[512], g_Bkv[512];
__device__ float g_Wf1[65536], g_Sf1[256], g_Bf1[256];

// ---------------- bf16 split helpers ----------------
__device__ __forceinline__ void split2(float x, float y, unsigned &hi, unsigned &lo)
{
    __nv_bfloat162 h = __floats2bfloat162_rn(x, y);
    float rx = x - __low2float(h);
    float ry = y - __high2float(h);
    __nv_bfloat162 l = __floats2bfloat162_rn(rx, ry);
    hi = *reinterpret_cast<unsigned*>(&h);
    lo = *reinterpret_cast<unsigned*>(&l);
}
__device__ __forceinline__ void mma_bf16(float* c, const unsigned* a, unsigned b0, unsigned b1)
{
    asm volatile(
        "mma.sync.aligned.m16n8k16.row.col.f32.bf16.bf16.f32 "
        "{%0,%1,%2,%3},{%4,%5,%6,%7},{%8,%9},{%0,%1,%2,%3};\n"
        : "+f"(c[0]), "+f"(c[1]), "+f"(c[2]), "+f"(c[3])
        : "r"(a[0]), "r"(a[1]), "r"(a[2]), "r"(a[3]), "r"(b0), "r"(b1));
}

// ---------------- weight fold: W' = W*lnw, S=sum(W'), b2=sum(W*lnb) ----------------
__global__ void prep_w(const float* __restrict__ qw,  const float* __restrict__ qlw,  const float* __restrict__ qlb,
                       const float* __restrict__ kvw, const float* __restrict__ kvlw, const float* __restrict__ kvlb,
                       const float* __restrict__ f1w, const float* __restrict__ flw,  const float* __restrict__ flb)
{
    int row = blockIdx.x;  // 0..1023
    const float *W, *lw, *lb; float *Wo, *So, *Bo; int o;
    if (row < 256)      { W=qw;  lw=qlw;  lb=qlb;  Wo=g_Wq;  So=g_Sq;  Bo=g_Bq;  o=row;     }
    else if (row < 768) { W=kvw; lw=kvlw; lb=kvlb; Wo=g_Wkv; So=g_Skv; Bo=g_Bkv; o=row-256; }
    else                { W=f1w; lw=flw;  lb=flb;  Wo=g_Wf1; So=g_Sf1; Bo=g_Bf1; o=row-768; }
    int c = threadIdx.x;
    float w  = W[o*256 + c];
    float wp = w * lw[c];
    Wo[o*256 + c] = wp;
    float bb = w * lb[c];
    __shared__ float r1[256], r2[256];
    r1[c] = wp; r2[c] = bb;
    __syncthreads();
    for (int s = 128; s > 0; s >>= 1) {
        if (c < s) { r1[c] += r1[c+s]; r2[c] += r2[c+s]; }
        __syncthreads();
    }
    if (c == 0) { So[o] = r1[0]; Bo[o] = r2[0]; }
}

// ---------------- per-pixel LN stats: thread-private over 4 pixels, float4 loads ----------------
// grid 64, block 256: thread handles 4 consecutive pixels across all 256 channels
__global__ void __launch_bounds__(256) ln_stats(const float* __restrict__ x,
                                                float* __restrict__ mu, float* __restrict__ rstd)
{
    long p0 = ((long)blockIdx.x * 256 + threadIdx.x) * 4;   // 4-aligned pixel idx
    int b = (int)(p0 >> 12);
    int n = (int)(p0 & 4095);
    const float* xp = x + (long)b*CHW + n;
    float4 s = make_float4(0.f,0.f,0.f,0.f);
    float4 q = make_float4(0.f,0.f,0.f,0.f);
    #pragma unroll 8
    for (int c = 0; c < 256; c++) {
        float4 v = *(const float4*)(xp + (long)c*HWn);
        s.x += v.x; q.x += v.x*v.x;
        s.y += v.y; q.y += v.y*v.y;
        s.z += v.z; q.z += v.z*v.z;
        s.w += v.w; q.w += v.w*v.w;
    }
    float4 m = make_float4(s.x*(1.f/256.f), s.y*(1.f/256.f), s.z*(1.f/256.f), s.w*(1.f/256.f));
    float4 r;
    r.x = rsqrtf(fmaxf(q.x*(1.f/256.f) - m.x*m.x, 0.f) + 1e-6f);
    r.y = rsqrtf(fmaxf(q.y*(1.f/256.f) - m.y*m.y, 0.f) + 1e-6f);
    r.z = rsqrtf(fmaxf(q.z*(1.f/256.f) - m.z*m.z, 0.f) + 1e-6f);
    r.w = rsqrtf(fmaxf(q.w*(1.f/256.f) - m.w*m.w, 0.f) + 1e-6f);
    *(float4*)(mu   + p0) = m;
    *(float4*)(rstd + p0) = r;
}

// ---------------- tensor-core 128x128x256 GEMM (3xBF16, pipelined 2-stage) ----------------
__global__ void __launch_bounds__(256) gemm_tc(
    const float* __restrict__ A,
    const float* __restrict__ X0, const float* __restrict__ X1, int split, long sX,
    float* __restrict__ Out, long sOut,
    const float* __restrict__ mu, const float* __restrict__ rstd,
    const float* __restrict__ Srow, const float* __restrict__ bias2,
    const float* __restrict__ bias,
    const float* __restrict__ Res, long sRes)
{
    int bz = blockIdx.z;
    const float* X   = (bz < split) ? X0 + (long)bz*sX : X1 + (long)(bz-split)*sX;
    float*       out = Out + (long)bz*sOut;
    const float* res = Res ? Res + (long)bz*sRes : (const float*)0;
    int n0 = blockIdx.x * 128, m0 = blockIdx.y * 128;

    __shared__ unsigned Ahs[2][8][136], Als[2][8][136];
    __shared__ unsigned Bhs[2][8][136], Bls[2][8][136];
    int tid  = threadIdx.x;
    int lane = tid & 31, wid = tid >> 5;
    int g = lane >> 2, l4 = lane & 3;
    int wm = wid >> 1, wn = wid & 1;

    int am  = tid >> 2;
    int akf = (tid & 3) << 2;
    int akp = akf >> 1;
    int bkp = tid >> 5, bng = (tid & 31) << 2;
    const float* arow0 = &A[(long)(m0+am)*256 + akf];
    const float* arow1 = &A[(long)(m0+am+64)*256 + akf];
    const float* brow  = &X[(long)(2*bkp)*HWn + n0 + bng];

    float acc[2][8][4];
    #pragma unroll
    for (int i = 0; i < 2; i++)
        #pragma unroll
        for (int j = 0; j < 8; j++)
            #pragma unroll
            for (int r = 0; r < 4; r++) acc[i][j][r] = 0.f;

    // prologue: chunk 0
    float4 pa0 = *(const float4*)(arow0);
    float4 pa1 = *(const float4*)(arow1);
    float4 pb0 = *(const float4*)(brow);
    float4 pb1 = *(const float4*)(brow + HWn);
    {
        unsigned h0,l0,h1,l1;
        split2(pa0.x, pa0.y, h0, l0); split2(pa0.z, pa0.w, h1, l1);
        Ahs[0][akp][am] = h0; Als[0][akp][am] = l0;
        Ahs[0][akp+1][am] = h1; Als[0][akp+1][am] = l1;
        split2(pa1.x, pa1.y, h0, l0); split2(pa1.z, pa1.w, h1, l1);
        Ahs[0][akp][am+64] = h0; Als[0][akp][am+64] = l0;
        Ahs[0][akp+1][am+64] = h1; Als[0][akp+1][am+64] = l1;
        unsigned b0h,b0l,b1h,b1l,b2h,b2l,b3h,b3l;
        split2(pb0.x, pb1.x, b0h, b0l);
        split2(pb0.y, pb1.y, b1h, b1l);
        split2(pb0.z, pb1.z, b2h, b2l);
        split2(pb0.w, pb1.w, b3h, b3l);
        *(uint4*)&Bhs[0][bkp][bng] = make_uint4(b0h,b1h,b2h,b3h);
        *(uint4*)&Bls[0][bkp][bng] = make_uint4(b0l,b1l,b2l,b3l);
    }
    __syncthreads();

    #pragma unroll
    for (int it = 0; it < 16; it++) {
        int s = it & 1;
        if (it < 15) {
            int k1 = (it + 1) * 16;
            pa0 = *(const float4*)(arow0 + k1);
            pa1 = *(const float4*)(arow1 + k1);
            pb0 = *(const float4*)(brow + (long)k1*HWn);
            pb1 = *(const float4*)(brow + (long)(k1+1)*HWn);
        }
        // fragments + MMA from stage s
        unsigned a_h[2][4], a_l[2][4];
        #pragma unroll
        for (int i = 0; i < 2; i++) {
            int row = wm*32 + i*16 + g;
            a_h[i][0]=Ahs[s][l4][row];   a_h[i][1]=Ahs[s][l4][row+8];
            a_h[i][2]=Ahs[s][l4+4][row]; a_h[i][3]=Ahs[s][l4+4][row+8];
            a_l[i][0]=Als[s][l4][row];   a_l[i][1]=Als[s][l4][row+8];
            a_l[i][2]=Als[s][l4+4][row]; a_l[i][3]=Als[s][l4+4][row+8];
        }
        #pragma unroll
        for (int j = 0; j < 8; j++) {
            int col = wn*64 + j*8 + g;
            unsigned bh0=Bhs[s][l4][col], bh1=Bhs[s][l4+4][col];
            unsigned bl0=Bls[s][l4][col], bl1=Bls[s][l4+4][col];
            #pragma unroll
            for (int i = 0; i < 2; i++) {
                mma_bf16(acc[i][j], a_h[i], bh0, bh1);
                mma_bf16(acc[i][j], a_l[i], bh0, bh1);
                mma_bf16(acc[i][j], a_h[i], bl0, bl1);
            }
        }
        if (it < 15) {
            int d = s ^ 1;
            unsigned h0,l0,h1,l1;
            split2(pa0.x, pa0.y, h0, l0); split2(pa0.z, pa0.w, h1, l1);
            Ahs[d][akp][am] = h0; Als[d][akp][am] = l0;
            Ahs[d][akp+1][am] = h1; Als[d][akp+1][am] = l1;
            split2(pa1.x, pa1.y, h0, l0); split2(pa1.z, pa1.w, h1, l1);
            Ahs[d][akp][am+64] = h0; Als[d][akp][am+64] = l0;
            Ahs[d][akp+1][am+64] = h1; Als[d][akp+1][am+64] = l1;
            unsigned b0h,b0l,b1h,b1l,b2h,b2l,b3h,b3l;
            split2(pb0.x, pb1.x, b0h, b0l);
            split2(pb0.y, pb1.y, b1h, b1l);
            split2(pb0.z, pb1.z, b2h, b2l);
            split2(pb0.w, pb1.w, b3h, b3l);
            *(uint4*)&Bhs[d][bkp][bng] = make_uint4(b0h,b1h,b2h,b3h);
            *(uint4*)&Bls[d][bkp][bng] = make_uint4(b0l,b1l,b2l,b3l);
        }
        __syncthreads();
    }

    #pragma unroll
    for (int i = 0; i < 2; i++) {
        #pragma unroll
        for (int h = 0; h < 2; h++) {
            int m = m0 + wm*32 + i*16 + g + h*8;
            float sr = 0.f, b2 = 0.f;
            if (mu)       { sr = Srow[m]; b2 = bias2[m]; }
            else if (bias){ b2 = bias[m]; }
            #pragma unroll
            for (int j = 0; j < 8; j++) {
                int n = n0 + wn*64 + j*8 + 2*l4;
                float v0 = acc[i][j][h*2+0], v1 = acc[i][j][h*2+1];
                if (mu) {
                    long p = (long)bz*HWn + n;
                    v0 = rstd[p  ]*(v0 - mu[p  ]*sr) + b2;
                    v1 = rstd[p+1]*(v1 - mu[p+1]*sr) + b2;
                } else {
                    v0 += b2; v1 += b2;
                    if (res) { v0 += res[(long)m*HWn + n]; v1 += res[(long)m*HWn + n + 1]; }
                }
                *(float2*)&out[(long)m*HWn + n] = make_float2(v0, v1);
            }
        }
    }
}

// ---------------- attention A1: raw scores + row norms (pipelined 2-stage) ----------------
__global__ void __launch_bounds__(256) attn_scores()
{
    int slab = blockIdx.x;      // 0..7
    int bh   = blockIdx.y;      // 0..63
    int b = bh >> 2, h = bh & 3;
    __shared__ unsigned Qh[2][8][72],  Ql[2][8][72];
    __shared__ unsigned Kh[2][8][136], Kl[2][8][136];
    int tid = threadIdx.x;
    int lane = tid & 31, wid = tid >> 5;
    int g = lane >> 2, l4 = lane & 3;
    int wm = wid >> 2, wn = wid & 3;

    int sc  = tid >> 2;
    int kf  = (tid & 3) << 2;
    int kp  = kf >> 1;
    const float* Qp  = g_q  + ((long)b*256 + h*64 + sc) * HWn + kf;
    const float* Kp0 = g_kv + ((long)b*512       + h*64 + sc) * HWn + kf;
    const float* Kp1 = g_kv + ((long)(b+16)*512  + h*64 + sc) * HWn + kf;

    float acc[2][4][4];
    #pragma unroll
    for (int i = 0; i < 2; i++)
        #pragma unroll
        for (int j = 0; j < 4; j++)
            #pragma unroll
            for (int r = 0; r < 4; r++) acc[i][j][r] = 0.f;
    float qn = 0.f, kn0 = 0.f, kn1 = 0.f;
    int n0 = slab * 512;

    float4 vq = *(const float4*)(Qp + n0);
    float4 v0 = *(const float4*)(Kp0 + n0);
    float4 v1 = *(const float4*)(Kp1 + n0);
    {
        qn  += vq.x*vq.x + vq.y*vq.y + vq.z*vq.z + vq.w*vq.w;
        kn0 += v0.x*v0.x + v0.y*v0.y + v0.z*v0.z + v0.w*v0.w;
        kn1 += v1.x*v1.x + v1.y*v1.y + v1.z*v1.z + v1.w*v1.w;
        unsigned h0,l0,h1,l1;
        split2(vq.x,vq.y,h0,l0); split2(vq.z,vq.w,h1,l1);
        Qh[0][kp][sc]=h0; Ql[0][kp][sc]=l0; Qh[0][kp+1][sc]=h1; Ql[0][kp+1][sc]=l1;
        split2(v0.x,v0.y,h0,l0); split2(v0.z,v0.w,h1,l1);
        Kh[0][kp][sc]=h0; Kl[0][kp][sc]=l0; Kh[0][kp+1][sc]=h1; Kl[0][kp+1][sc]=l1;
        split2(v1.x,v1.y,h0,l0); split2(v1.z,v1.w,h1,l1);
        Kh[0][kp][sc+64]=h0; Kl[0][kp][sc+64]=l0; Kh[0][kp+1][sc+64]=h1; Kl[0][kp+1][sc+64]=l1;
    }
    __syncthreads();

    #pragma unroll 4
    for (int it = 0; it < 32; it++) {
        int s = it & 1;
        if (it < 31) {
            int nc = n0 + (it+1)*16;
            vq = *(const float4*)(Qp + nc);
            v0 = *(const float4*)(Kp0 + nc);
            v1 = *(const float4*)(Kp1 + nc);
        }
        unsigned a_h[2][4], a_l[2][4];
        #pragma unroll
        for (int i = 0; i < 2; i++) {
            int row = wm*32 + i*16 + g;
            a_h[i][0]=Qh[s][l4][row];   a_h[i][1]=Qh[s][l4][row+8];
            a_h[i][2]=Qh[s][l4+4][row]; a_h[i][3]=Qh[s][l4+4][row+8];
            a_l[i][0]=Ql[s][l4][row];   a_l[i][1]=Ql[s][l4][row+8];
            a_l[i][2]=Ql[s][l4+4][row]; a_l[i][3]=Ql[s][l4+4][row+8];
        }
        #pragma unroll
        for (int j = 0; j < 4; j++) {
            int col = wn*32 + j*8 + g;
            unsigned bh0=Kh[s][l4][col], bh1=Kh[s][l4+4][col];
            unsigned bl0=Kl[s][l4][col], bl1=Kl[s][l4+4][col];
            #pragma unroll
            for (int i = 0; i < 2; i++) {
                mma_bf16(acc[i][j], a_h[i], bh0, bh1);
                mma_bf16(acc[i][j], a_l[i], bh0, bh1);
                mma_bf16(acc[i][j], a_h[i], bl0, bl1);
            }
        }
        if (it < 31) {
            int d = s ^ 1;
            qn  += vq.x*vq.x + vq.y*vq.y + vq.z*vq.z + vq.w*vq.w;
            kn0 += v0.x*v0.x + v0.y*v0.y + v0.z*v0.z + v0.w*v0.w;
            kn1 += v1.x*v1.x + v1.y*v1.y + v1.z*v1.z + v1.w*v1.w;
            unsigned h0,l0,h1,l1;
            split2(vq.x,vq.y,h0,l0); split2(vq.z,vq.w,h1,l1);
            Qh[d][kp][sc]=h0; Ql[d][kp][sc]=l0; Qh[d][kp+1][sc]=h1; Ql[d][kp+1][sc]=l1;
            split2(v0.x,v0.y,h0,l0); split2(v0.z,v0.w,h1,l1);
            Kh[d][kp][sc]=h0; Kl[d][kp][sc]=l0; Kh[d][kp+1][sc]=h1; Kl[d][kp+1][sc]=l1;
            split2(v1.x,v1.y,h0,l0); split2(v1.z,v1.w,h1,l1);
            Kh[d][kp][sc+64]=h0; Kl[d][kp][sc+64]=l0; Kh[d][kp+1][sc+64]=h1; Kl[d][kp+1][sc+64]=l1;
        }
        __syncthreads();
    }
    long base = (long)slab*64 + bh;
    float* Sp = g_S + base*64*128;
    #pragma unroll
    for (int i = 0; i < 2; i++)
        #pragma unroll
        for (int h2 = 0; h2 < 2; h2++) {
            int row = wm*32 + i*16 + g + h2*8;
            #pragma unroll
            for (int j = 0; j < 4; j++) {
                int col = wn*32 + j*8 + 2*l4;
                *(float2*)&Sp[row*128 + col] = make_float2(acc[i][j][h2*2], acc[i][j][h2*2+1]);
            }
        }
    qn  += __shfl_xor_sync(0xffffffffu, qn, 1);  qn  += __shfl_xor_sync(0xffffffffu, qn, 2);
    kn0 += __shfl_xor_sync(0xffffffffu, kn0, 1); kn0 += __shfl_xor_sync(0xffffffffu, kn0, 2);
    kn1 += __shfl_xor_sync(0xffffffffu, kn1, 1); kn1 += __shfl_xor_sync(0xffffffffu, kn1, 2);
    if ((tid & 3) == 0) {
        g_qn2[base*64  + sc]      = qn;
        g_kn2[base*128 + sc]      = kn0;
        g_kn2[base*128 + sc + 64] = kn1;
    }
}

// ---------------- attention A2: combine, normalize, softmax, fold gate ----------------
__global__ void __launch_bounds__(128) attn_softmax(const float* __restrict__ attn_scale)
{
    int bh = blockIdx.x; int h = bh & 3;
    __shared__ float qn[64], kn[128];
    int tid = threadIdx.x;
    if (tid < 64) {
        float s = 0.f;
        for (int sl = 0; sl < NSPL; sl++) s += g_qn2[((long)sl*64 + bh)*64 + tid];
        qn[tid] = fmaxf(sqrtf(s), 1e-12f);
    }
    {
        float s = 0.f;
        for (int sl = 0; sl < NSPL; sl++) s += g_kn2[((long)sl*64 + bh)*128 + tid];
        kn[tid] = fmaxf(sqrtf(s), 1e-12f);
    }
    __syncthreads();
    int c = tid & 63, half = tid >> 6;
    float v[64];
    const float* Sp = g_S + (long)bh*64*128 + c*128 + half*64;
    float iq = 1.0f / qn[c];
    #pragma unroll
    for (int d = 0; d < 64; d++) {
        float s = 0.f;
        for (int sl = 0; sl < NSPL; sl++) s += Sp[(long)sl*64*64*128 + d];
        v[d] = s * iq / kn[half*64 + d];
    }
    float mx = -1e30f;
    #pragma unroll
    for (int d = 0; d < 64; d++) mx = fmaxf(mx, v[d]);
    float sum = 0.f;
    #pragma unroll
    for (int d = 0; d < 64; d++) { v[d] = expf(v[d] - mx); sum += v[d]; }
    float gg  = 1.0f / (1.0f + expf(-attn_scale[h]));
    float fac = (half == 0 ? gg : 1.0f - gg) / sum;
    float* P = g_P + (long)bh*64*128 + c*128 + half*64;
    #pragma unroll
    for (int d = 0; d < 64; d++) P[d] = v[d] * fac;
}

// ---------------- attention A3: O = P(64x128) * [Vtex;Vdep](128xHW) (pipelined) ----------------
__global__ void __launch_bounds__(256) attn_pv()
{
    int nt = blockIdx.x;   // 0..31
    int bh = blockIdx.y;
    int b = bh >> 2, h = bh & 3;
    __shared__ unsigned Ph[64][72], Pl[64][72];
    __shared__ unsigned Vh[2][8][136], Vl[2][8][136];
    int tid = threadIdx.x;
    int lane = tid & 31, wid = tid >> 5;
    int g = lane >> 2, l4 = lane & 3;
    int wm = wid >> 2, wn = wid & 3;

    int vkp = tid >> 5, vng = (tid & 31) << 2;
    int n0 = nt * 128;
    // V row pointers for this thread: chunk c uses dd = 16*c + 2*vkp
    const float* vbase0 = g_kv + ((long)b*512      + 256 + h*64) * HWn + n0 + vng;
    const float* vbase1 = g_kv + ((long)(b+16)*512 + 256 + h*64) * HWn + n0 + vng;

    // stage P fully
    const float* P = g_P + (long)bh*64*128;
    #pragma unroll
    for (int q = 0; q < 8; q++) {
        int qi = tid + 256*q;
        int c  = qi & 63;
        int df = (qi >> 6) << 2;
        float4 v = *(const float4*)(P + c*128 + df);
        unsigned h0,l0,h1,l1;
        split2(v.x,v.y,h0,l0); split2(v.z,v.w,h1,l1);
        int kp = df >> 1;
        Ph[kp][c]=h0; Pl[kp][c]=l0; Ph[kp+1][c]=h1; Pl[kp+1][c]=l1;
    }
    float acc[2][4][4];
    #pragma unroll
    for (int i = 0; i < 2; i++)
        #pragma unroll
        for (int j = 0; j < 4; j++)
            #pragma unroll
            for (int r = 0; r < 4; r++) acc[i][j][r] = 0.f;

    // prologue: V chunk 0 (dd = 2*vkp, all < 64 -> tex region)
    float4 r0 = *(const float4*)(vbase0 + (long)(2*vkp)*HWn);
    float4 r1 = *(const float4*)(vbase0 + (long)(2*vkp+1)*HWn);
    {
        unsigned h0,l0,h1,l1,h2,l2,h3,l3;
        split2(r0.x, r1.x, h0, l0);
        split2(r0.y, r1.y, h1, l1);
        split2(r0.z, r1.z, h2, l2);
        split2(r0.w, r1.w, h3, l3);
        *(uint4*)&Vh[0][vkp][vng] = make_uint4(h0,h1,h2,h3);
        *(uint4*)&Vl[0][vkp][vng] = make_uint4(l0,l1,l2,l3);
    }
    __syncthreads();

    #pragma unroll
    for (int it = 0; it < 8; it++) {
        int s = it & 1;
        if (it < 7) {
            int dd = (it+1)*16 + 2*vkp;
            const float* vp = (dd < 64) ? vbase0 + (long)dd*HWn
                                        : vbase1 + (long)(dd-64)*HWn;
            r0 = *(const float4*)(vp);
            r1 = *(const float4*)(vp + HWn);
        }
        int kb = it * 8;
        unsigned a_h[2][4], a_l[2][4];
        #pragma unroll
        for (int i = 0; i < 2; i++) {
            int row = wm*32 + i*16 + g;
            a_h[i][0]=Ph[kb+l4][row];   a_h[i][1]=Ph[kb+l4][row+8];
            a_h[i][2]=Ph[kb+l4+4][row]; a_h[i][3]=Ph[kb+l4+4][row+8];
            a_l[i][0]=Pl[kb+l4][row];   a_l[i][1]=Pl[kb+l4][row+8];
            a_l[i][2]=Pl[kb+l4+4][row]; a_l[i][3]=Pl[kb+l4+4][row+8];
        }
        #pragma unroll
        for (int j = 0; j < 4; j++) {
            int col = wn*32 + j*8 + g;
            unsigned bh0=Vh[s][l4][col], bh1=Vh[s][l4+4][col];
            unsigned bl0=Vl[s][l4][col], bl1=Vl[s][l4+4][col];
            #pragma unroll
            for (int i = 0; i < 2; i++) {
                mma_bf16(acc[i][j], a_h[i], bh0, bh1);
                mma_bf16(acc[i][j], a_l[i], bh0, bh1);
                mma_bf16(acc[i][j], a_h[i], bl0, bl1);
            }
        }
        if (it < 7) {
            int d = s ^ 1;
            unsigned h0,l0,h1,l1,h2,l2,h3,l3;
            split2(r0.x, r1.x, h0, l0);
            split2(r0.y, r1.y, h1, l1);
            split2(r0.z, r1.z, h2, l2);
            split2(r0.w, r1.w, h3, l3);
            *(uint4*)&Vh[d][vkp][vng] = make_uint4(h0,h1,h2,h3);
            *(uint4*)&Vl[d][vkp][vng] = make_uint4(l0,l1,l2,l3);
        }
        __syncthreads();
    }
    float* O = g_attn + ((long)b*256 + h*64) * HWn;
    #pragma unroll
    for (int i = 0; i < 2; i++)
        #pragma unroll
        for (int h2 = 0; h2 < 2; h2++) {
            int row = wm*32 + i*16 + g + h2*8;
            #pragma unroll
            for (int j = 0; j < 4; j++) {
                int col = wn*32 + j*8 + 2*l4;
                *(float2*)(O + (long)row*HWn + n0 + col) =
                    make_float2(acc[i][j][h2*2], acc[i][j][h2*2+1]);
            }
        }
}

// ---------------- depthwise 3x3 SAME + exact GELU ----------------
__global__ void dwconv_gelu(const float* __restrict__ dww)
{
    int bc = blockIdx.x;
    int c  = bc & 255;
    int hh = blockIdx.y * 4 + threadIdx.y;
    int tx = threadIdx.x;
    const float* in = g_y1 + (long)bc * HWn;
    float s = 0.f;
    #pragma unroll
    for (int di = -1; di <= 1; di++) {
        int hi = hh + di;
        if (hi < 0 || hi > 63) continue;
        #pragma unroll
        for (int dj = -1; dj <= 1; dj++) {
            int wj = tx + dj;
            if (wj < 0 || wj > 63) continue;
            s = fmaf(in[hi*64 + wj], dww[c*9 + (di+1)*3 + (dj+1)], s);
        }
    }
    float g = 0.5f * s * (1.0f + erff(s * 0.70710678118654752f));
    g_y2[(long)bc * HWn + hh*64 + tx] = g;
}

// ---------------- launch ----------------
extern "C" void kernel_launch(void* const* d_in, const int* in_sizes, int n_in,
                              void* d_out, int out_size)
{
    const float* img    = (const float*)d_in[0];
    const float* tex    = (const float*)d_in[1];
    const float* dep    = (const float*)d_in[2];
    const float* qnw    = (const float*)d_in[3];
    const float* qnb    = (const float*)d_in[4];
    const float* kvnw   = (const float*)d_in[5];
    const float* kvnb   = (const float*)d_in[6];
    const float* ascale = (const float*)d_in[7];
    const float* qpw    = (const float*)d_in[8];
    const float* kvpw   = (const float*)d_in[9];
    const float* opw    = (const float*)d_in[10];
    const float* opb    = (const float*)d_in[11];
    const float* fnw    = (const float*)d_in[12];
    const float* fnb    = (const float*)d_in[13];
    const float* f1w    = (const float*)d_in[14];
    const float* dww    = (const float*)d_in[15];
    const float* f2w    = (const float*)d_in[16];
    float* outp = (float*)d_out;

    float *p_q,*p_kv,*p_attn,*p_x,*p_y1,*p_y2;
    float *p_muq,*p_rsq,*p_mukv,*p_rskv,*p_mux,*p_rsx;
    float *p_Wq,*p_Sq,*p_Bq,*p_Wkv,*p_Skv,*p_Bkv,*p_Wf1,*p_Sf1,*p_Bf1;
    cudaGetSymbolAddress((void**)&p_q,    g_q);
    cudaGetSymbolAddress((void**)&p_kv,   g_kv);
    cudaGetSymbolAddress((void**)&p_attn, g_attn);
    cudaGetSymbolAddress((void**)&p_x,    g_x);
    cudaGetSymbolAddress((void**)&p_y1,   g_y1);
    cudaGetSymbolAddress((void**)&p_y2,   g_y2);
    cudaGetSymbolAddress((void**)&p_muq,  g_muq);
    cudaGetSymbolAddress((void**)&p_rsq,  g_rsq);
    cudaGetSymbolAddress((void**)&p_mukv, g_mukv);
    cudaGetSymbolAddress((void**)&p_rskv, g_rskv);
    cudaGetSymbolAddress((void**)&p_mux,  g_mux);
    cudaGetSymbolAddress((void**)&p_rsx,  g_rsx);
    cudaGetSymbolAddress((void**)&p_Wq,   g_Wq);
    cudaGetSymbolAddress((void**)&p_Sq,   g_Sq);
    cudaGetSymbolAddress((void**)&p_Bq,   g_Bq);
    cudaGetSymbolAddress((void**)&p_Wkv,  g_Wkv);
    cudaGetSymbolAddress((void**)&p_Skv,  g_Skv);
    cudaGetSymbolAddress((void**)&p_Bkv,  g_Bkv);
    cudaGetSymbolAddress((void**)&p_Wf1,  g_Wf1);
    cudaGetSymbolAddress((void**)&p_Sf1,  g_Sf1);
    cudaGetSymbolAddress((void**)&p_Bf1,  g_Bf1);

    // 0) fold LN weights into GEMM weights
    prep_w<<<1024, 256>>>(qpw,qnw,qnb, kvpw,kvnw,kvnb, f1w,fnw,fnb);
    // 1) LN stats
    ln_stats<<<64, 256>>>(img, p_muq,  p_rsq);
    ln_stats<<<64, 256>>>(tex, p_mukv, p_rskv);
    ln_stats<<<64, 256>>>(dep, p_mukv + 65536, p_rskv + 65536);
    // 2) q = Wq' @ img  (LN folded in epilogue)
    gemm_tc<<<dim3(32,2,16), 256>>>(p_Wq, img, img, 99, CHW, p_q, CHW,
                                    p_muq, p_rsq, p_Sq, p_Bq, nullptr, nullptr, 0);
    // 3) kv = Wkv' @ [tex;dep]
    gemm_tc<<<dim3(32,4,32), 256>>>(p_Wkv, tex, dep, 16, CHW, p_kv, 512L*HWn,
                                    p_mukv, p_rskv, p_Skv, p_Bkv, nullptr, nullptr, 0);
    // 4) attention
    attn_scores <<<dim3(NSPL,64), 256>>>();
    attn_softmax<<<64, 128>>>(ascale);
    attn_pv     <<<dim3(32,64), 256>>>();
    // 5) x = img + Wo @ attn + bias
    gemm_tc<<<dim3(32,2,16), 256>>>(opw, p_attn, p_attn, 99, CHW, p_x, CHW,
                                    nullptr, nullptr, nullptr, nullptr, opb, img, CHW);
    // 6) ffn
    ln_stats<<<64, 256>>>(p_x, p_mux, p_rsx);
    gemm_tc<<<dim3(32,2,16), 256>>>(p_Wf1, p_x, p_x, 99, CHW, p_y1, CHW,
                                    p_mux, p_rsx, p_Sf1, p_Bf1, nullptr, nullptr, 0);
    dwconv_gelu<<<dim3(4096,16), dim3(64,4)>>>(dww);
    // 7) out = x + fc2 @ y2
    gemm_tc<<<dim3(32,2,16), 256>>>(f2w, p_y2, p_y2, 99, CHW, outp, CHW,
                                    nullptr, nullptr, nullptr, nullptr, nullptr, p_x, CHW);
}

// round 9
// speedup vs baseline: 1.2934x; 1.2934x over previous
#include <cuda_runtime.h>
#include <cuda_fp16.h>
#include <math.h>

// Problem constants
#define Bn   16
#define Cc   256
#define HWn  4096
#define NHh  4
#define HDd  64
#define CHW  1048576L   // C*HW
#define NSPL 8          // n-split slabs for attention scores

// ---------------- scratch (static __device__ — no allocation allowed) ----------------
__device__ float g_q[16777216];      // (B,256,HW)
__device__ float g_kv[67108864];     // (2B,512,HW)
__device__ float g_attn[16777216];   // (B,256,HW)
__device__ float g_x[16777216];      // residual mid
__device__ float g_y1[16777216];
__device__ float g_y2[16777216];
__device__ float g_S[NSPL*64*64*128];   // score partials [slab][bh][c][dd]
__device__ float g_qn2[NSPL*64*64];
__device__ float g_kn2[NSPL*64*128];
__device__ float g_P[64*64*128];        // gated softmax probs [bh][c][dd]
__device__ float g_muq[65536],  g_rsq[65536];
__device__ float g_mukv[131072],g_rskv[131072];
__device__ float g_mux[65536],  g_rsx[65536];
__device__ float g_Wq[65536],  g_Sq[256],  g_Bq[256];
__device__ float g_Wkv[131072],g_Skv[512], g_Bkv[512];
__device__ float g_Wf1[65536], g_Sf1[256], g_Bf1[256];

// ---------------- fp16 helpers ----------------
// pack (x,y) k-pair into one 32-bit reg of 2 fp16
__device__ __forceinline__ unsigned pack2h(float x, float y)
{
    __half2 h = __floats2half2_rn(x, y);
    return *reinterpret_cast<unsigned*>(&h);
}
// split: hi = RN_fp16(v), lo = RN_fp16(v - hi)
__device__ __forceinline__ void split2h(float x, float y, unsigned &hi, unsigned &lo)
{
    __half2 h = __floats2half2_rn(x, y);
    float rx = x - __low2float(h);
    float ry = y - __high2float(h);
    __half2 l = __floats2half2_rn(rx, ry);
    hi = *reinterpret_cast<unsigned*>(&h);
    lo = *reinterpret_cast<unsigned*>(&l);
}
__device__ __forceinline__ void mma_f16(float* c, const unsigned* a, unsigned b0, unsigned b1)
{
    asm volatile(
        "mma.sync.aligned.m16n8k16.row.col.f32.f16.f16.f32 "
        "{%0,%1,%2,%3},{%4,%5,%6,%7},{%8,%9},{%0,%1,%2,%3};\n"
        : "+f"(c[0]), "+f"(c[1]), "+f"(c[2]), "+f"(c[3])
        : "r"(a[0]), "r"(a[1]), "r"(a[2]), "r"(a[3]), "r"(b0), "r"(b1));
}

// ---------------- weight fold: W' = W*lnw, S=sum(W'), b2=sum(W*lnb) ----------------
__global__ void prep_w(const float* __restrict__ qw,  const float* __restrict__ qlw,  const float* __restrict__ qlb,
                       const float* __restrict__ kvw, const float* __restrict__ kvlw, const float* __restrict__ kvlb,
                       const float* __restrict__ f1w, const float* __restrict__ flw,  const float* __restrict__ flb)
{
    int row = blockIdx.x;  // 0..1023
    const float *W, *lw, *lb; float *Wo, *So, *Bo; int o;
    if (row < 256)      { W=qw;  lw=qlw;  lb=qlb;  Wo=g_Wq;  So=g_Sq;  Bo=g_Bq;  o=row;     }
    else if (row < 768) { W=kvw; lw=kvlw; lb=kvlb; Wo=g_Wkv; So=g_Skv; Bo=g_Bkv; o=row-256; }
    else                { W=f1w; lw=flw;  lb=flb;  Wo=g_Wf1; So=g_Sf1; Bo=g_Bf1; o=row-768; }
    int c = threadIdx.x;
    float w  = W[o*256 + c];
    float wp = w * lw[c];
    Wo[o*256 + c] = wp;
    float bb = w * lb[c];
    __shared__ float r1[256], r2[256];
    r1[c] = wp; r2[c] = bb;
    __syncthreads();
    for (int s = 128; s > 0; s >>= 1) {
        if (c < s) { r1[c] += r1[c+s]; r2[c] += r2[c+s]; }
        __syncthreads();
    }
    if (c == 0) { So[o] = r1[0]; Bo[o] = r2[0]; }
}

// ---------------- per-pixel LN stats (mean over C=256 channels) ----------------
__global__ void __launch_bounds__(256) ln_stats(const float* __restrict__ x,
                                                float* __restrict__ mu, float* __restrict__ rstd)
{
    __shared__ float s1[4][64], s2[4][64];
    int tid = threadIdx.x;
    int pl  = tid & 63, cg = tid >> 6;
    long pix = (long)blockIdx.x * 64 + pl;
    int b = (int)(pix >> 12);
    int n = (int)(pix & 4095);
    const float* xp = x + (long)b*CHW + n;
    float a = 0.f, a2 = 0.f;
    #pragma unroll 8
    for (int c = cg*64; c < cg*64 + 64; c++) { float v = xp[(long)c*HWn]; a += v; a2 += v*v; }
    s1[cg][pl] = a; s2[cg][pl] = a2;
    __syncthreads();
    if (tid < 64) {
        float t1 = s1[0][tid]+s1[1][tid]+s1[2][tid]+s1[3][tid];
        float t2 = s2[0][tid]+s2[1][tid]+s2[2][tid]+s2[3][tid];
        float m   = t1 * (1.0f/256.0f);
        float var = t2 * (1.0f/256.0f) - m*m;
        long p = (long)blockIdx.x*64 + tid;
        mu[p]   = m;
        rstd[p] = rsqrtf(fmaxf(var, 0.0f) + 1e-6f);
    }
}

// ---------------- tensor-core 128x128x256 GEMM (2xFP16: A split, B single) ----------------
// out[bz][m][n] = epilogue( sum_c A[m][c] * X[bz][c][n] )
__global__ void __launch_bounds__(256) gemm_tc(
    const float* __restrict__ A,
    const float* __restrict__ X0, const float* __restrict__ X1, int split, long sX,
    float* __restrict__ Out, long sOut,
    const float* __restrict__ mu, const float* __restrict__ rstd,
    const float* __restrict__ Srow, const float* __restrict__ bias2,
    const float* __restrict__ bias,
    const float* __restrict__ Res, long sRes)
{
    int bz = blockIdx.z;
    const float* X   = (bz < split) ? X0 + (long)bz*sX : X1 + (long)(bz-split)*sX;
    float*       out = Out + (long)bz*sOut;
    const float* res = Res ? Res + (long)bz*sRes : (const float*)0;
    int n0 = blockIdx.x * 128, m0 = blockIdx.y * 128;

    __shared__ unsigned Ahs[8][136], Als[8][136];  // [kp][m]
    __shared__ unsigned Bhs[8][136];               // [kp][n]
    int tid  = threadIdx.x;
    int lane = tid & 31, wid = tid >> 5;
    int g = lane >> 2, l4 = lane & 3;
    int wm = wid >> 1, wn = wid & 1;

    int am  = tid >> 2;
    int akf = (tid & 3) << 2;
    int bkp = tid >> 5, bng = (tid & 31) << 2;

    float acc[2][8][4];
    #pragma unroll
    for (int i = 0; i < 2; i++)
        #pragma unroll
        for (int j = 0; j < 8; j++)
            #pragma unroll
            for (int r = 0; r < 4; r++) acc[i][j][r] = 0.f;

    for (int k0 = 0; k0 < 256; k0 += 16) {
        // ---- stage A (128 x 16) split ----
        #pragma unroll
        for (int q = 0; q < 2; q++) {
            int m = am + q*64;
            float4 v = *(const float4*)&A[(long)(m0+m)*256 + k0 + akf];
            unsigned h0,l0,h1,l1;
            split2h(v.x, v.y, h0, l0);
            split2h(v.z, v.w, h1, l1);
            int kp = akf >> 1;
            Ahs[kp][m] = h0; Als[kp][m] = l0;
            Ahs[kp+1][m] = h1; Als[kp+1][m] = l1;
        }
        // ---- stage B (16 x 128) hi only ----
        {
            const float* rp = &X[(long)(k0 + 2*bkp)*HWn + n0 + bng];
            float4 r0 = *(const float4*)rp;
            float4 r1 = *(const float4*)(rp + HWn);
            *(uint4*)&Bhs[bkp][bng] = make_uint4(
                pack2h(r0.x, r1.x), pack2h(r0.y, r1.y),
                pack2h(r0.z, r1.z), pack2h(r0.w, r1.w));
        }
        __syncthreads();
        unsigned a_h[2][4], a_l[2][4];
        #pragma unroll
        for (int i = 0; i < 2; i++) {
            int row = wm*32 + i*16 + g;
            a_h[i][0]=Ahs[l4][row];   a_h[i][1]=Ahs[l4][row+8];
            a_h[i][2]=Ahs[l4+4][row]; a_h[i][3]=Ahs[l4+4][row+8];
            a_l[i][0]=Als[l4][row];   a_l[i][1]=Als[l4][row+8];
            a_l[i][2]=Als[l4+4][row]; a_l[i][3]=Als[l4+4][row+8];
        }
        #pragma unroll
        for (int j = 0; j < 8; j++) {
            int col = wn*64 + j*8 + g;
            unsigned bh0=Bhs[l4][col], bh1=Bhs[l4+4][col];
            #pragma unroll
            for (int i = 0; i < 2; i++) {
                mma_f16(acc[i][j], a_h[i], bh0, bh1);
                mma_f16(acc[i][j], a_l[i], bh0, bh1);
            }
        }
        __syncthreads();
    }

    #pragma unroll
    for (int i = 0; i < 2; i++) {
        #pragma unroll
        for (int h = 0; h < 2; h++) {
            int m = m0 + wm*32 + i*16 + g + h*8;
            float sr = 0.f, b2 = 0.f;
            if (mu)       { sr = Srow[m]; b2 = bias2[m]; }
            else if (bias){ b2 = bias[m]; }
            #pragma unroll
            for (int j = 0; j < 8; j++) {
                int n = n0 + wn*64 + j*8 + 2*l4;
                float v0 = acc[i][j][h*2+0], v1 = acc[i][j][h*2+1];
                if (mu) {
                    long p = (long)bz*HWn + n;
                    v0 = rstd[p  ]*(v0 - mu[p  ]*sr) + b2;
                    v1 = rstd[p+1]*(v1 - mu[p+1]*sr) + b2;
                } else {
                    v0 += b2; v1 += b2;
                    if (res) { v0 += res[(long)m*HWn + n]; v1 += res[(long)m*HWn + n + 1]; }
                }
                *(float2*)&out[(long)m*HWn + n] = make_float2(v0, v1);
            }
        }
    }
}

// ---------------- attention A1: raw scores Q*[Ktex;Kdep]^T partials + row norms ----------------
__global__ void __launch_bounds__(256) attn_scores()
{
    int slab = blockIdx.x;      // 0..7
    int bh   = blockIdx.y;      // 0..63
    int b = bh >> 2, h = bh & 3;
    __shared__ unsigned Qh[8][72],  Ql[8][72];    // [kp][c] split
    __shared__ unsigned Kh[8][136];               // [kp][dd] single
    int tid = threadIdx.x;
    int lane = tid & 31, wid = tid >> 5;
    int g = lane >> 2, l4 = lane & 3;
    int wm = wid >> 2, wn = wid & 3;

    int sc  = tid >> 2;
    int kf  = (tid & 3) << 2;
    int kp  = kf >> 1;
    const float* Qp  = g_q  + ((long)b*256 + h*64 + sc) * HWn + kf;
    const float* Kp0 = g_kv + ((long)b*512       + h*64 + sc) * HWn + kf;
    const float* Kp1 = g_kv + ((long)(b+16)*512  + h*64 + sc) * HWn + kf;

    float acc[2][4][4];
    #pragma unroll
    for (int i = 0; i < 2; i++)
        #pragma unroll
        for (int j = 0; j < 4; j++)
            #pragma unroll
            for (int r = 0; r < 4; r++) acc[i][j][r] = 0.f;
    float qn = 0.f, kn0 = 0.f, kn1 = 0.f;
    int n0 = slab * 512;

    for (int nc = n0; nc < n0 + 512; nc += 16) {
        {
            float4 v = *(const float4*)(Qp + nc);
            qn += v.x*v.x + v.y*v.y + v.z*v.z + v.w*v.w;
            unsigned h0,l0,h1,l1;
            split2h(v.x,v.y,h0,l0); split2h(v.z,v.w,h1,l1);
            Qh[kp][sc]=h0; Ql[kp][sc]=l0; Qh[kp+1][sc]=h1; Ql[kp+1][sc]=l1;
        }
        {
            float4 v = *(const float4*)(Kp0 + nc);
            kn0 += v.x*v.x + v.y*v.y + v.z*v.z + v.w*v.w;
            Kh[kp][sc]   = pack2h(v.x, v.y);
            Kh[kp+1][sc] = pack2h(v.z, v.w);
        }
        {
            float4 v = *(const float4*)(Kp1 + nc);
            kn1 += v.x*v.x + v.y*v.y + v.z*v.z + v.w*v.w;
            Kh[kp][sc+64]   = pack2h(v.x, v.y);
            Kh[kp+1][sc+64] = pack2h(v.z, v.w);
        }
        __syncthreads();
        unsigned a_h[2][4], a_l[2][4];
        #pragma unroll
        for (int i = 0; i < 2; i++) {
            int row = wm*32 + i*16 + g;
            a_h[i][0]=Qh[l4][row];   a_h[i][1]=Qh[l4][row+8];
            a_h[i][2]=Qh[l4+4][row]; a_h[i][3]=Qh[l4+4][row+8];
            a_l[i][0]=Ql[l4][row];   a_l[i][1]=Ql[l4][row+8];
            a_l[i][2]=Ql[l4+4][row]; a_l[i][3]=Ql[l4+4][row+8];
        }
        #pragma unroll
        for (int j = 0; j < 4; j++) {
            int col = wn*32 + j*8 + g;
            unsigned bh0=Kh[l4][col], bh1=Kh[l4+4][col];
            #pragma unroll
            for (int i = 0; i < 2; i++) {
                mma_f16(acc[i][j], a_h[i], bh0, bh1);
                mma_f16(acc[i][j], a_l[i], bh0, bh1);
            }
        }
        __syncthreads();
    }
    long base = (long)slab*64 + bh;
    float* Sp = g_S + base*64*128;
    #pragma unroll
    for (int i = 0; i < 2; i++)
        #pragma unroll
        for (int h2 = 0; h2 < 2; h2++) {
            int row = wm*32 + i*16 + g + h2*8;
            #pragma unroll
            for (int j = 0; j < 4; j++) {
                int col = wn*32 + j*8 + 2*l4;
                *(float2*)&Sp[row*128 + col] = make_float2(acc[i][j][h2*2], acc[i][j][h2*2+1]);
            }
        }
    qn  += __shfl_xor_sync(0xffffffffu, qn, 1);  qn  += __shfl_xor_sync(0xffffffffu, qn, 2);
    kn0 += __shfl_xor_sync(0xffffffffu, kn0, 1); kn0 += __shfl_xor_sync(0xffffffffu, kn0, 2);
    kn1 += __shfl_xor_sync(0xffffffffu, kn1, 1); kn1 += __shfl_xor_sync(0xffffffffu, kn1, 2);
    if ((tid & 3) == 0) {
        g_qn2[base*64  + sc]      = qn;
        g_kn2[base*128 + sc]      = kn0;
        g_kn2[base*128 + sc + 64] = kn1;
    }
}

// ---------------- attention A2: combine partials, normalize, softmax, fold gate ----------------
__global__ void __launch_bounds__(128) attn_softmax(const float* __restrict__ attn_scale)
{
    int bh = blockIdx.x; int h = bh & 3;
    __shared__ float qn[64], kn[128];
    int tid = threadIdx.x;
    if (tid < 64) {
        float s = 0.f;
        for (int sl = 0; sl < NSPL; sl++) s += g_qn2[((long)sl*64 + bh)*64 + tid];
        qn[tid] = fmaxf(sqrtf(s), 1e-12f);
    }
    {
        float s = 0.f;
        for (int sl = 0; sl < NSPL; sl++) s += g_kn2[((long)sl*64 + bh)*128 + tid];
        kn[tid] = fmaxf(sqrtf(s), 1e-12f);
    }
    __syncthreads();
    int c = tid & 63, half = tid >> 6;
    float v[64];
    const float* Sp = g_S + (long)bh*64*128 + c*128 + half*64;
    float iq = 1.0f / qn[c];
    #pragma unroll
    for (int d = 0; d < 64; d++) {
        float s = 0.f;
        for (int sl = 0; sl < NSPL; sl++) s += Sp[(long)sl*64*64*128 + d];
        v[d] = s * iq / kn[half*64 + d];
    }
    float mx = -1e30f;
    #pragma unroll
    for (int d = 0; d < 64; d++) mx = fmaxf(mx, v[d]);
    float sum = 0.f;
    #pragma unroll
    for (int d = 0; d < 64; d++) { v[d] = expf(v[d] - mx); sum += v[d]; }
    float gg  = 1.0f / (1.0f + expf(-attn_scale[h]));
    float fac = (half == 0 ? gg : 1.0f - gg) / sum;
    float* P = g_P + (long)bh*64*128 + c*128 + half*64;
    #pragma unroll
    for (int d = 0; d < 64; d++) P[d] = v[d] * fac;
}

// ---------------- attention A3: O = P_comb(64x128) * [Vtex;Vdep](128xHW) ----------------
__global__ void __launch_bounds__(256) attn_pv()
{
    int nt = blockIdx.x;   // 0..31 (128 cols each)
    int bh = blockIdx.y;
    int b = bh >> 2, h = bh & 3;
    __shared__ unsigned Ph[64][72], Pl[64][72];   // all 64 k-pairs of P (split)
    __shared__ unsigned Vh[8][136];               // one 16-dd chunk of V (single)
    int tid = threadIdx.x;
    int lane = tid & 31, wid = tid >> 5;
    int g = lane >> 2, l4 = lane & 3;
    int wm = wid >> 2, wn = wid & 3;

    // stage P fully (split)
    const float* P = g_P + (long)bh*64*128;
    #pragma unroll
    for (int q = 0; q < 8; q++) {
        int qi = tid + 256*q;
        int c  = qi & 63;
        int df = (qi >> 6) << 2;
        float4 v = *(const float4*)(P + c*128 + df);
        unsigned h0,l0,h1,l1;
        split2h(v.x,v.y,h0,l0); split2h(v.z,v.w,h1,l1);
        int kp = df >> 1;
        Ph[kp][c]=h0; Pl[kp][c]=l0; Ph[kp+1][c]=h1; Pl[kp+1][c]=l1;
    }
    int vkp = tid >> 5, vng = (tid & 31) << 2;
    int n0 = nt * 128;
    float acc[2][4][4];
    #pragma unroll
    for (int i = 0; i < 2; i++)
        #pragma unroll
        for (int j = 0; j < 4; j++)
            #pragma unroll
            for (int r = 0; r < 4; r++) acc[i][j][r] = 0.f;
    __syncthreads();

    for (int d0 = 0; d0 < 128; d0 += 16) {
        int dd = d0 + 2*vkp;
        const float* vp = (dd < 64)
            ? g_kv + ((long)b*512      + 256 + h*64 + dd       )*HWn
            : g_kv + ((long)(b+16)*512 + 256 + h*64 + (dd - 64))*HWn;
        float4 r0 = *(const float4*)(vp + n0 + vng);
        float4 r1 = *(const float4*)(vp + HWn + n0 + vng);
        *(uint4*)&Vh[vkp][vng] = make_uint4(
            pack2h(r0.x, r1.x), pack2h(r0.y, r1.y),
            pack2h(r0.z, r1.z), pack2h(r0.w, r1.w));
        __syncthreads();
        int kb = d0 >> 1;
        unsigned a_h[2][4], a_l[2][4];
        #pragma unroll
        for (int i = 0; i < 2; i++) {
            int row = wm*32 + i*16 + g;
            a_h[i][0]=Ph[kb+l4][row];   a_h[i][1]=Ph[kb+l4][row+8];
            a_h[i][2]=Ph[kb+l4+4][row]; a_h[i][3]=Ph[kb+l4+4][row+8];
            a_l[i][0]=Pl[kb+l4][row];   a_l[i][1]=Pl[kb+l4][row+8];
            a_l[i][2]=Pl[kb+l4+4][row]; a_l[i][3]=Pl[kb+l4+4][row+8];
        }
        #pragma unroll
        for (int j = 0; j < 4; j++) {
            int col = wn*32 + j*8 + g;
            unsigned bh0=Vh[l4][col], bh1=Vh[l4+4][col];
            #pragma unroll
            for (int i = 0; i < 2; i++) {
                mma_f16(acc[i][j], a_h[i], bh0, bh1);
                mma_f16(acc[i][j], a_l[i], bh0, bh1);
            }
        }
        __syncthreads();
    }
    float* O = g_attn + ((long)b*256 + h*64) * HWn;
    #pragma unroll
    for (int i = 0; i < 2; i++)
        #pragma unroll
        for (int h2 = 0; h2 < 2; h2++) {
            int row = wm*32 + i*16 + g + h2*8;
            #pragma unroll
            for (int j = 0; j < 4; j++) {
                int col = wn*32 + j*8 + 2*l4;
                *(float2*)(O + (long)row*HWn + n0 + col) =
                    make_float2(acc[i][j][h2*2], acc[i][j][h2*2+1]);
            }
        }
}

// ---------------- depthwise 3x3 SAME + exact GELU ----------------
__global__ void dwconv_gelu(const float* __restrict__ dww)
{
    int bc = blockIdx.x;
    int c  = bc & 255;
    int hh = blockIdx.y * 4 + threadIdx.y;
    int tx = threadIdx.x;
    const float* in = g_y1 + (long)bc * HWn;
    float s = 0.f;
    #pragma unroll
    for (int di = -1; di <= 1; di++) {
        int hi = hh + di;
        if (hi < 0 || hi > 63) continue;
        #pragma unroll
        for (int dj = -1; dj <= 1; dj++) {
            int wj = tx + dj;
            if (wj < 0 || wj > 63) continue;
            s = fmaf(in[hi*64 + wj], dww[c*9 + (di+1)*3 + (dj+1)], s);
        }
    }
    float g = 0.5f * s * (1.0f + erff(s * 0.70710678118654752f));
    g_y2[(long)bc * HWn + hh*64 + tx] = g;
}

// ---------------- launch ----------------
extern "C" void kernel_launch(void* const* d_in, const int* in_sizes, int n_in,
                              void* d_out, int out_size)
{
    const float* img    = (const float*)d_in[0];
    const float* tex    = (const float*)d_in[1];
    const float* dep    = (const float*)d_in[2];
    const float* qnw    = (const float*)d_in[3];
    const float* qnb    = (const float*)d_in[4];
    const float* kvnw   = (const float*)d_in[5];
    const float* kvnb   = (const float*)d_in[6];
    const float* ascale = (const float*)d_in[7];
    const float* qpw    = (const float*)d_in[8];
    const float* kvpw   = (const float*)d_in[9];
    const float* opw    = (const float*)d_in[10];
    const float* opb    = (const float*)d_in[11];
    const float* fnw    = (const float*)d_in[12];
    const float* fnb    = (const float*)d_in[13];
    const float* f1w    = (const float*)d_in[14];
    const float* dww    = (const float*)d_in[15];
    const float* f2w    = (const float*)d_in[16];
    float* outp = (float*)d_out;

    float *p_q,*p_kv,*p_attn,*p_x,*p_y1,*p_y2;
    float *p_muq,*p_rsq,*p_mukv,*p_rskv,*p_mux,*p_rsx;
    float *p_Wq,*p_Sq,*p_Bq,*p_Wkv,*p_Skv,*p_Bkv,*p_Wf1,*p_Sf1,*p_Bf1;
    cudaGetSymbolAddress((void**)&p_q,    g_q);
    cudaGetSymbolAddress((void**)&p_kv,   g_kv);
    cudaGetSymbolAddress((void**)&p_attn, g_attn);
    cudaGetSymbolAddress((void**)&p_x,    g_x);
    cudaGetSymbolAddress((void**)&p_y1,   g_y1);
    cudaGetSymbolAddress((void**)&p_y2,   g_y2);
    cudaGetSymbolAddress((void**)&p_muq,  g_muq);
    cudaGetSymbolAddress((void**)&p_rsq,  g_rsq);
    cudaGetSymbolAddress((void**)&p_mukv, g_mukv);
    cudaGetSymbolAddress((void**)&p_rskv, g_rskv);
    cudaGetSymbolAddress((void**)&p_mux,  g_mux);
    cudaGetSymbolAddress((void**)&p_rsx,  g_rsx);
    cudaGetSymbolAddress((void**)&p_Wq,   g_Wq);
    cudaGetSymbolAddress((void**)&p_Sq,   g_Sq);
    cudaGetSymbolAddress((void**)&p_Bq,   g_Bq);
    cudaGetSymbolAddress((void**)&p_Wkv,  g_Wkv);
    cudaGetSymbolAddress((void**)&p_Skv,  g_Skv);
    cudaGetSymbolAddress((void**)&p_Bkv,  g_Bkv);
    cudaGetSymbolAddress((void**)&p_Wf1,  g_Wf1);
    cudaGetSymbolAddress((void**)&p_Sf1,  g_Sf1);
    cudaGetSymbolAddress((void**)&p_Bf1,  g_Bf1);

    // 0) fold LN weights into GEMM weights
    prep_w<<<1024, 256>>>(qpw,qnw,qnb, kvpw,kvnw,kvnb, f1w,fnw,fnb);
    // 1) LN stats
    ln_stats<<<1024, 256>>>(img, p_muq,  p_rsq);
    ln_stats<<<1024, 256>>>(tex, p_mukv, p_rskv);
    ln_stats<<<1024, 256>>>(dep, p_mukv + 65536, p_rskv + 65536);
    // 2) q = Wq' @ img  (LN folded in epilogue)
    gemm_tc<<<dim3(32,2,16), 256>>>(p_Wq, img, img, 99, CHW, p_q, CHW,
                                    p_muq, p_rsq, p_Sq, p_Bq, nullptr, nullptr, 0);
    // 3) kv = Wkv' @ [tex;dep]
    gemm_tc<<<dim3(32,4,32), 256>>>(p_Wkv, tex, dep, 16, CHW, p_kv, 512L*HWn,
                                    p_mukv, p_rskv, p_Skv, p_Bkv, nullptr, nullptr, 0);
    // 4) attention
    attn_scores <<<dim3(NSPL,64), 256>>>();
    attn_softmax<<<64, 128>>>(ascale);
    attn_pv     <<<dim3(32,64), 256>>>();
    // 5) x = img + Wo @ attn + bias
    gemm_tc<<<dim3(32,2,16), 256>>>(opw, p_attn, p_attn, 99, CHW, p_x, CHW,
                                    nullptr, nullptr, nullptr, nullptr, opb, img, CHW);
    // 6) ffn
    ln_stats<<<1024, 256>>>(p_x, p_mux, p_rsx);
    gemm_tc<<<dim3(32,2,16), 256>>>(p_Wf1, p_x, p_x, 99, CHW, p_y1, CHW,
                                    p_mux, p_rsx, p_Sf1, p_Bf1, nullptr, nullptr, 0);
    dwconv_gelu<<<dim3(4096,16), dim3(64,4)>>>(dww);
    // 7) out = x + fc2 @ y2
    gemm_tc<<<dim3(32,2,16), 256>>>(f2w, p_y2, p_y2, 99, CHW, outp, CHW,
                                    nullptr, nullptr, nullptr, nullptr, nullptr, p_x, CHW);
}